// round 3
// baseline (speedup 1.0000x reference)
#include <cuda_runtime.h>

#define SEQ 1024
#define NB  48
#define NROWS (NB * SEQ)            // 49152 rows, 9 channels
#define NBLK_A 288                   // 3 attns * 48 batches * 2 row-halves
#define TPB_A 512

typedef unsigned long long ull;

// scratch (allocation-free rule: __device__ globals)
__device__ float g_att[9 * NROWS];      // SoA: [channel][row]
__device__ float g_part[NBLK_A * 6];    // per-block partial sum/sumsq (3 ch)
__device__ float g_ss[18];              // BN scale[9], shift[9]

// ---------------- packed f32x2 helpers (Blackwell) ----------------
__device__ __forceinline__ ull pack2(float lo, float hi) {
    ull r; asm("mov.b64 %0, {%1, %2};" : "=l"(r) : "f"(lo), "f"(hi)); return r;
}
__device__ __forceinline__ void unpack2(ull v, float& lo, float& hi) {
    asm("mov.b64 {%0, %1}, %2;" : "=f"(lo), "=f"(hi) : "l"(v));
}
__device__ __forceinline__ ull fma2(ull a, ull b, ull c) {
    ull d; asm("fma.rn.f32x2 %0, %1, %2, %3;" : "=l"(d) : "l"(a), "l"(b), "l"(c)); return d;
}
__device__ __forceinline__ ull mul2(ull a, ull b) {
    ull d; asm("mul.rn.f32x2 %0, %1, %2;" : "=l"(d) : "l"(a), "l"(b)); return d;
}
__device__ __forceinline__ ull add2(ull a, ull b) {
    ull d; asm("add.rn.f32x2 %0, %1, %2;" : "=l"(d) : "l"(a), "l"(b)); return d;
}
__device__ __forceinline__ ull ex2_2(ull d) {
    ull e;
    asm("{\n\t"
        ".reg .f32 dl, dh, el, eh;\n\t"
        "mov.b64 {dl, dh}, %1;\n\t"
        "ex2.approx.f32 el, dl;\n\t"
        "ex2.approx.f32 eh, dh;\n\t"
        "mov.b64 %0, {el, eh};\n\t"
        "}" : "=l"(e) : "l"(d));
    return e;
}

// ---------------------------------------------------------------------------
// Kernel A: fused projection + cross attention (packed f32x2) + BN partials
// block = (attn, batch, row-half). Full K/V tile in smem; thread owns 1 row.
// 288 blocks -> 2 blocks/SM -> 32 warps/SM (occ 50%).
// ---------------------------------------------------------------------------
__global__ __launch_bounds__(TPB_A, 2) void attn_kernel(
    const float* __restrict__ x,
    const float* __restrict__ WQ, const float* __restrict__ bQ,
    const float* __restrict__ WK, const float* __restrict__ bK,
    const float* __restrict__ WV, const float* __restrict__ bV)
{
    __shared__ __align__(16) float Kx[SEQ], Ky[SEQ], Kz[SEQ];
    __shared__ __align__(16) float Vx[SEQ], Vy[SEQ], Vz[SEQ];
    __shared__ float sred[16 * 6];

    const int blk  = blockIdx.x;
    const int attn = blk / (NB * 2);
    const int rem  = blk - attn * (NB * 2);
    const int b    = rem >> 1;
    const int half = rem & 1;

    // a1=attn(Q2,K0,V1), a2=attn(Q0,K1,V2), a3=attn(Q1,K2,V0)
    const int qmap[3] = {2, 0, 1};
    const int vmap[3] = {1, 2, 0};
    const int qb = qmap[attn], kb = attn, vb = vmap[attn];

    const int tid = threadIdx.x;

    // ---- phase 1: K,V tiles (3x3 projection on the fly) ----
    {
        const float* wk = WK + kb * 9;  const float* bk = bK + kb * 3;
        const float* wv = WV + vb * 9;  const float* bv = bV + vb * 3;
        #pragma unroll
        for (int it = 0; it < SEQ / TPB_A; ++it) {
            int t = tid + it * TPB_A;
            const float* xk = x + ((size_t)(kb * NB + b) * SEQ + t) * 3;
            float x0 = xk[0], x1 = xk[1], x2 = xk[2];
            Kx[t] = fmaf(wk[0], x0, fmaf(wk[1], x1, fmaf(wk[2], x2, bk[0])));
            Ky[t] = fmaf(wk[3], x0, fmaf(wk[4], x1, fmaf(wk[5], x2, bk[1])));
            Kz[t] = fmaf(wk[6], x0, fmaf(wk[7], x1, fmaf(wk[8], x2, bk[2])));

            const float* xv = x + ((size_t)(vb * NB + b) * SEQ + t) * 3;
            float y0 = xv[0], y1 = xv[1], y2 = xv[2];
            Vx[t] = fmaf(wv[0], y0, fmaf(wv[1], y1, fmaf(wv[2], y2, bv[0])));
            Vy[t] = fmaf(wv[3], y0, fmaf(wv[4], y1, fmaf(wv[5], y2, bv[1])));
            Vz[t] = fmaf(wv[6], y0, fmaf(wv[7], y1, fmaf(wv[8], y2, bv[2])));
        }
    }
    __syncthreads();

    // ---- per-thread Q for row = half*512 + tid; fold log2e/sqrt(3) ----
    const int row = half * TPB_A + tid;
    const float qscale = 1.4426950408889634f / 1.7320508075688772f;
    ull qx, qy, qz;
    {
        const float* wq = WQ + qb * 9;  const float* bq = bQ + qb * 3;
        const float* xq = x + ((size_t)(qb * NB + b) * SEQ + row) * 3;
        float x0 = xq[0], x1 = xq[1], x2 = xq[2];
        float a = fmaf(wq[0], x0, fmaf(wq[1], x1, fmaf(wq[2], x2, bq[0]))) * qscale;
        float c = fmaf(wq[3], x0, fmaf(wq[4], x1, fmaf(wq[5], x2, bq[1]))) * qscale;
        float d = fmaf(wq[6], x0, fmaf(wq[7], x1, fmaf(wq[8], x2, bq[2]))) * qscale;
        qx = pack2(a, a); qy = pack2(c, c); qz = pack2(d, d);
    }

    const ulonglong2* pKx = (const ulonglong2*)Kx;
    const ulonglong2* pKy = (const ulonglong2*)Ky;
    const ulonglong2* pKz = (const ulonglong2*)Kz;
    const ulonglong2* pVx = (const ulonglong2*)Vx;
    const ulonglong2* pVy = (const ulonglong2*)Vy;
    const ulonglong2* pVz = (const ulonglong2*)Vz;

    ull ax = 0, ay = 0, az = 0, aw = 0;

    #pragma unroll 2
    for (int g = 0; g < SEQ / 4; ++g) {         // 4 t-values per group
        ulonglong2 kx = pKx[g], ky = pKy[g], kz = pKz[g];
        ulonglong2 vx = pVx[g], vy = pVy[g], vz = pVz[g];

        ull d0 = fma2(qx, kx.x, fma2(qy, ky.x, mul2(qz, kz.x)));
        ull e0 = ex2_2(d0);
        ax = fma2(e0, vx.x, ax);
        ay = fma2(e0, vy.x, ay);
        az = fma2(e0, vz.x, az);
        aw = add2(aw, e0);

        ull d1 = fma2(qx, kx.y, fma2(qy, ky.y, mul2(qz, kz.y)));
        ull e1 = ex2_2(d1);
        ax = fma2(e1, vx.y, ax);
        ay = fma2(e1, vy.y, ay);
        az = fma2(e1, vz.y, az);
        aw = add2(aw, e1);
    }

    // horizontal reduce packed halves
    float l, h;
    unpack2(aw, l, h); const float inv = 1.0f / (l + h);
    unpack2(ax, l, h); const float o0 = (l + h) * inv;
    unpack2(ay, l, h); const float o1 = (l + h) * inv;
    unpack2(az, l, h); const float o2 = (l + h) * inv;

    // SoA coalesced store
    {
        const size_t r = (size_t)b * SEQ + row;
        g_att[(size_t)(attn * 3 + 0) * NROWS + r] = o0;
        g_att[(size_t)(attn * 3 + 1) * NROWS + r] = o1;
        g_att[(size_t)(attn * 3 + 2) * NROWS + r] = o2;
    }

    // ---- BN partial stats (deterministic) ----
    float sm[3] = {o0, o1, o2};
    float sq[3] = {o0 * o0, o1 * o1, o2 * o2};
    #pragma unroll
    for (int off = 16; off > 0; off >>= 1) {
        #pragma unroll
        for (int i = 0; i < 3; ++i) {
            sm[i] += __shfl_down_sync(0xFFFFFFFFu, sm[i], off);
            sq[i] += __shfl_down_sync(0xFFFFFFFFu, sq[i], off);
        }
    }
    const int warp = tid >> 5, lane = tid & 31;
    if (lane == 0) {
        #pragma unroll
        for (int i = 0; i < 3; ++i) {
            sred[warp * 6 + i]     = sm[i];
            sred[warp * 6 + 3 + i] = sq[i];
        }
    }
    __syncthreads();
    if (tid == 0) {
        float acc[6] = {0.f, 0.f, 0.f, 0.f, 0.f, 0.f};
        #pragma unroll
        for (int w = 0; w < 16; ++w)
            #pragma unroll
            for (int i = 0; i < 6; ++i)
                acc[i] += sred[w * 6 + i];
        #pragma unroll
        for (int i = 0; i < 6; ++i)
            g_part[blk * 6 + i] = acc[i];
    }
}

// ---------------------------------------------------------------------------
// Kernel C: finalize BN stats once (1 block; warp w = channel w)
// ---------------------------------------------------------------------------
__global__ __launch_bounds__(288) void stats_kernel(
    const float* __restrict__ gamma, const float* __restrict__ beta)
{
    const int w = threadIdx.x >> 5, lane = threadIdx.x & 31;
    if (w >= 9) return;
    const int at = w / 3, d = w - at * 3;
    float sm = 0.f, sq = 0.f;
    for (int i = lane; i < NB * 2; i += 32) {           // 96 blocks per attn
        const float* p = g_part + (size_t)(at * NB * 2 + i) * 6;
        sm += p[d];
        sq += p[3 + d];
    }
    #pragma unroll
    for (int off = 16; off > 0; off >>= 1) {
        sm += __shfl_down_sync(0xFFFFFFFFu, sm, off);
        sq += __shfl_down_sync(0xFFFFFFFFu, sq, off);
    }
    if (lane == 0) {
        const float mean = sm * (1.0f / NROWS);
        const float var  = sq * (1.0f / NROWS) - mean * mean;
        const float inv  = rsqrtf(var + 1e-5f);
        const float sc   = gamma[w] * inv;
        g_ss[w]     = sc;
        g_ss[9 + w] = beta[w] - mean * sc;
    }
}

// ---------------------------------------------------------------------------
// Kernel B: BN + FC. 4 consecutive rows/thread -> float4 LDG + float4 STG.
// ---------------------------------------------------------------------------
__global__ __launch_bounds__(256) void bnfc_kernel(
    const float* __restrict__ fcw, const float* __restrict__ fcb,
    float* __restrict__ out)
{
    __shared__ float ss[18];
    __shared__ float w[27];   // fcw transposed-ish copy
    const int tid = threadIdx.x;
    if (tid < 18) ss[tid] = g_ss[tid];
    if (tid < 27) w[tid] = fcw[tid];
    __syncthreads();

    const int r0 = (blockIdx.x * 256 + tid) * 4;   // grid covers NROWS exactly
    float n[4][9];
    #pragma unroll
    for (int c = 0; c < 9; ++c) {
        float4 v = *(const float4*)(g_att + (size_t)c * NROWS + r0);
        n[0][c] = fmaf(v.x, ss[c], ss[9 + c]);
        n[1][c] = fmaf(v.y, ss[c], ss[9 + c]);
        n[2][c] = fmaf(v.z, ss[c], ss[9 + c]);
        n[3][c] = fmaf(v.w, ss[c], ss[9 + c]);
    }
    float y[4][3];
    #pragma unroll
    for (int r = 0; r < 4; ++r)
        #pragma unroll
        for (int j = 0; j < 3; ++j) {
            float acc = fcb[j];
            #pragma unroll
            for (int c = 0; c < 9; ++c)
                acc = fmaf(n[r][c], w[j * 9 + c], acc);
            y[r][j] = acc;
        }
    float4* o = (float4*)(out + (size_t)r0 * 3);
    o[0] = make_float4(y[0][0], y[0][1], y[0][2], y[1][0]);
    o[1] = make_float4(y[1][1], y[1][2], y[2][0], y[2][1]);
    o[2] = make_float4(y[2][2], y[3][0], y[3][1], y[3][2]);
}

// ---------------------------------------------------------------------------
extern "C" void kernel_launch(void* const* d_in, const int* in_sizes, int n_in,
                              void* d_out, int out_size)
{
    const float* x     = (const float*)d_in[0];
    const float* WQ    = (const float*)d_in[1];
    const float* bQ    = (const float*)d_in[2];
    const float* WK    = (const float*)d_in[3];
    const float* bK    = (const float*)d_in[4];
    const float* WV    = (const float*)d_in[5];
    const float* bV    = (const float*)d_in[6];
    const float* gamma = (const float*)d_in[7];
    const float* beta  = (const float*)d_in[8];
    const float* fcw   = (const float*)d_in[9];
    const float* fcb   = (const float*)d_in[10];

    attn_kernel<<<NBLK_A, TPB_A>>>(x, WQ, bQ, WK, bK, WV, bV);
    stats_kernel<<<1, 288>>>(gamma, beta);
    bnfc_kernel<<<NROWS / 1024, 256>>>(fcw, fcb, (float*)d_out);
}

// round 4
// speedup vs baseline: 1.0071x; 1.0071x over previous
#include <cuda_runtime.h>

#define SEQ 1024
#define NB  48
#define NROWS (NB * SEQ)            // 49152 rows, 9 channels
#define NBLK_A 288                   // 3 attns * 48 batches * 2 row-halves
#define TPB_A 512

typedef unsigned long long ull;

// scratch (allocation-free rule: __device__ globals)
__device__ float g_att[9 * NROWS];      // SoA: [channel][row]
__device__ float g_part[NBLK_A * 6];    // per-block partial sum/sumsq (3 ch)
__device__ float g_ss[18];              // BN scale[9], shift[9]

// ---------------- packed f32x2 helpers (Blackwell) ----------------
__device__ __forceinline__ ull pack2(float lo, float hi) {
    ull r; asm("mov.b64 %0, {%1, %2};" : "=l"(r) : "f"(lo), "f"(hi)); return r;
}
__device__ __forceinline__ void unpack2(ull v, float& lo, float& hi) {
    asm("mov.b64 {%0, %1}, %2;" : "=f"(lo), "=f"(hi) : "l"(v));
}
__device__ __forceinline__ ull fma2(ull a, ull b, ull c) {
    ull d; asm("fma.rn.f32x2 %0, %1, %2, %3;" : "=l"(d) : "l"(a), "l"(b), "l"(c)); return d;
}
__device__ __forceinline__ ull mul2(ull a, ull b) {
    ull d; asm("mul.rn.f32x2 %0, %1, %2;" : "=l"(d) : "l"(a), "l"(b)); return d;
}
__device__ __forceinline__ ull add2(ull a, ull b) {
    ull d; asm("add.rn.f32x2 %0, %1, %2;" : "=l"(d) : "l"(a), "l"(b)); return d;
}
__device__ __forceinline__ ull ex2_2(ull d) {
    ull e;
    asm("{\n\t"
        ".reg .f32 dl, dh, el, eh;\n\t"
        "mov.b64 {dl, dh}, %1;\n\t"
        "ex2.approx.f32 el, dl;\n\t"
        "ex2.approx.f32 eh, dh;\n\t"
        "mov.b64 %0, {el, eh};\n\t"
        "}" : "=l"(e) : "l"(d));
    return e;
}

// ---------------------------------------------------------------------------
// Kernel A: fused projection + cross attention + BN partials.
// block = (attn, batch, row-half). Warp's thalf bit picks t-half [0,512) or
// [512,1024). Each thread: 2 rows x 512 t. Warp-uniform smem broadcast.
// ---------------------------------------------------------------------------
__global__ __launch_bounds__(TPB_A, 2) void attn_kernel(
    const float* __restrict__ x,
    const float* __restrict__ WQ, const float* __restrict__ bQ,
    const float* __restrict__ WK, const float* __restrict__ bK,
    const float* __restrict__ WV, const float* __restrict__ bV)
{
    __shared__ __align__(16) float Kx[SEQ], Ky[SEQ], Kz[SEQ];
    __shared__ __align__(16) float Vx[SEQ], Vy[SEQ], Vz[SEQ];
    __shared__ __align__(16) float4 cbuf[256][2];   // thalf=1 partials
    __shared__ float sred[16 * 6];

    const int blk  = blockIdx.x;
    const int attn = blk / (NB * 2);
    const int rem  = blk - attn * (NB * 2);
    const int b    = rem >> 1;
    const int rhalf = rem & 1;          // which 512-row half of the batch

    // a1=attn(Q2,K0,V1), a2=attn(Q0,K1,V2), a3=attn(Q1,K2,V0)
    const int qmap[3] = {2, 0, 1};
    const int vmap[3] = {1, 2, 0};
    const int qb = qmap[attn], kb = attn, vb = vmap[attn];

    const int tid   = threadIdx.x;
    const int warp  = tid >> 5;
    const int lane  = tid & 31;
    const int thalf = warp & 1;          // t-half this warp sums
    const int pairId = warp >> 1;        // 0..7
    const int slot  = pairId * 32 + lane;   // 0..255 (combine slot / row id)

    // ---- phase 1: K,V tiles (3x3 projection on the fly) ----
    {
        const float* wk = WK + kb * 9;  const float* bk = bK + kb * 3;
        const float* wv = WV + vb * 9;  const float* bv = bV + vb * 3;
        #pragma unroll
        for (int it = 0; it < SEQ / TPB_A; ++it) {
            int t = tid + it * TPB_A;
            const float* xk = x + ((size_t)(kb * NB + b) * SEQ + t) * 3;
            float x0 = xk[0], x1 = xk[1], x2 = xk[2];
            Kx[t] = fmaf(wk[0], x0, fmaf(wk[1], x1, fmaf(wk[2], x2, bk[0])));
            Ky[t] = fmaf(wk[3], x0, fmaf(wk[4], x1, fmaf(wk[5], x2, bk[1])));
            Kz[t] = fmaf(wk[6], x0, fmaf(wk[7], x1, fmaf(wk[8], x2, bk[2])));

            const float* xv = x + ((size_t)(vb * NB + b) * SEQ + t) * 3;
            float y0 = xv[0], y1 = xv[1], y2 = xv[2];
            Vx[t] = fmaf(wv[0], y0, fmaf(wv[1], y1, fmaf(wv[2], y2, bv[0])));
            Vy[t] = fmaf(wv[3], y0, fmaf(wv[4], y1, fmaf(wv[5], y2, bv[1])));
            Vz[t] = fmaf(wv[6], y0, fmaf(wv[7], y1, fmaf(wv[8], y2, bv[2])));
        }
    }
    __syncthreads();

    // ---- per-thread Q for rows r0 = slot, r1 = slot + 256 (within half) ----
    const float qscale = 1.4426950408889634f / 1.7320508075688772f;
    ull q0x, q0y, q0z, q1x, q1y, q1z;
    {
        const float* wq = WQ + qb * 9;  const float* bq = bQ + qb * 3;
        const int rbase = rhalf * 512;
        const float* xq = x + ((size_t)(qb * NB + b) * SEQ + rbase + slot) * 3;
        float x0 = xq[0], x1 = xq[1], x2 = xq[2];
        float a = fmaf(wq[0], x0, fmaf(wq[1], x1, fmaf(wq[2], x2, bq[0]))) * qscale;
        float c = fmaf(wq[3], x0, fmaf(wq[4], x1, fmaf(wq[5], x2, bq[1]))) * qscale;
        float d = fmaf(wq[6], x0, fmaf(wq[7], x1, fmaf(wq[8], x2, bq[2]))) * qscale;
        q0x = pack2(a, a); q0y = pack2(c, c); q0z = pack2(d, d);
        xq = x + ((size_t)(qb * NB + b) * SEQ + rbase + slot + 256) * 3;
        x0 = xq[0]; x1 = xq[1]; x2 = xq[2];
        a = fmaf(wq[0], x0, fmaf(wq[1], x1, fmaf(wq[2], x2, bq[0]))) * qscale;
        c = fmaf(wq[3], x0, fmaf(wq[4], x1, fmaf(wq[5], x2, bq[1]))) * qscale;
        d = fmaf(wq[6], x0, fmaf(wq[7], x1, fmaf(wq[8], x2, bq[2]))) * qscale;
        q1x = pack2(a, a); q1y = pack2(c, c); q1z = pack2(d, d);
    }

    const ulonglong2* pKx = (const ulonglong2*)Kx;
    const ulonglong2* pKy = (const ulonglong2*)Ky;
    const ulonglong2* pKz = (const ulonglong2*)Kz;
    const ulonglong2* pVx = (const ulonglong2*)Vx;
    const ulonglong2* pVy = (const ulonglong2*)Vy;
    const ulonglong2* pVz = (const ulonglong2*)Vz;

    ull ax0 = 0, ay0 = 0, az0 = 0, aw0 = 0;
    ull ax1 = 0, ay1 = 0, az1 = 0, aw1 = 0;

    const int g0 = thalf * (SEQ / 8);    // 128 groups of 4 t per t-half
    #pragma unroll 2
    for (int g = g0; g < g0 + SEQ / 8; ++g) {
        ulonglong2 kx = pKx[g], ky = pKy[g], kz = pKz[g];
        ull d00 = fma2(q0x, kx.x, fma2(q0y, pKy[g].x, mul2(q0z, kz.x)));
        ull d01 = fma2(q0x, kx.y, fma2(q0y, ky.y, mul2(q0z, kz.y)));
        ull d10 = fma2(q1x, kx.x, fma2(q1y, ky.x, mul2(q1z, kz.x)));
        ull d11 = fma2(q1x, kx.y, fma2(q1y, ky.y, mul2(q1z, kz.y)));
        ull e00 = ex2_2(d00);
        ull e01 = ex2_2(d01);
        ull e10 = ex2_2(d10);
        ull e11 = ex2_2(d11);
        ulonglong2 vx = pVx[g], vy = pVy[g], vz = pVz[g];
        ax0 = fma2(e00, vx.x, ax0);  ay0 = fma2(e00, vy.x, ay0);
        az0 = fma2(e00, vz.x, az0);  aw0 = add2(aw0, e00);
        ax0 = fma2(e01, vx.y, ax0);  ay0 = fma2(e01, vy.y, ay0);
        az0 = fma2(e01, vz.y, az0);  aw0 = add2(aw0, e01);
        ax1 = fma2(e10, vx.x, ax1);  ay1 = fma2(e10, vy.x, ay1);
        az1 = fma2(e10, vz.x, az1);  aw1 = add2(aw1, e10);
        ax1 = fma2(e11, vx.y, ax1);  ay1 = fma2(e11, vy.y, ay1);
        az1 = fma2(e11, vz.y, az1);  aw1 = add2(aw1, e11);
    }

    // horizontal reduce packed halves -> per-row partial (num, den)
    float l, h;
    float n00, n01, n02, dd0, n10, n11, n12, dd1;
    unpack2(ax0, l, h); n00 = l + h;
    unpack2(ay0, l, h); n01 = l + h;
    unpack2(az0, l, h); n02 = l + h;
    unpack2(aw0, l, h); dd0 = l + h;
    unpack2(ax1, l, h); n10 = l + h;
    unpack2(ay1, l, h); n11 = l + h;
    unpack2(az1, l, h); n12 = l + h;
    unpack2(aw1, l, h); dd1 = l + h;

    // combine t-halves across warp pairs via smem
    if (thalf == 1) {
        cbuf[slot][0] = make_float4(n00, n01, n02, dd0);
        cbuf[slot][1] = make_float4(n10, n11, n12, dd1);
    }
    __syncthreads();

    float o00 = 0.f, o01 = 0.f, o02 = 0.f, o10 = 0.f, o11 = 0.f, o12 = 0.f;
    if (thalf == 0) {
        float4 p0 = cbuf[slot][0];
        float4 p1 = cbuf[slot][1];
        const float inv0 = 1.0f / (dd0 + p0.w);
        const float inv1 = 1.0f / (dd1 + p1.w);
        o00 = (n00 + p0.x) * inv0; o01 = (n01 + p0.y) * inv0; o02 = (n02 + p0.z) * inv0;
        o10 = (n10 + p1.x) * inv1; o11 = (n11 + p1.y) * inv1; o12 = (n12 + p1.z) * inv1;

        const size_t r0 = (size_t)b * SEQ + rhalf * 512 + slot;
        const size_t r1 = r0 + 256;
        float* c0 = g_att + (size_t)(attn * 3 + 0) * NROWS;
        float* c1 = g_att + (size_t)(attn * 3 + 1) * NROWS;
        float* c2 = g_att + (size_t)(attn * 3 + 2) * NROWS;
        c0[r0] = o00; c1[r0] = o01; c2[r0] = o02;
        c0[r1] = o10; c1[r1] = o11; c2[r1] = o12;
    }

    // ---- BN partial stats (thalf=1 warps contribute zeros) ----
    float sm[3], sq[3];
    sm[0] = o00 + o10; sm[1] = o01 + o11; sm[2] = o02 + o12;
    sq[0] = o00 * o00 + o10 * o10;
    sq[1] = o01 * o01 + o11 * o11;
    sq[2] = o02 * o02 + o12 * o12;
    #pragma unroll
    for (int off = 16; off > 0; off >>= 1) {
        #pragma unroll
        for (int i = 0; i < 3; ++i) {
            sm[i] += __shfl_down_sync(0xFFFFFFFFu, sm[i], off);
            sq[i] += __shfl_down_sync(0xFFFFFFFFu, sq[i], off);
        }
    }
    if (lane == 0) {
        #pragma unroll
        for (int i = 0; i < 3; ++i) {
            sred[warp * 6 + i]     = sm[i];
            sred[warp * 6 + 3 + i] = sq[i];
        }
    }
    __syncthreads();
    if (tid == 0) {
        float acc[6] = {0.f, 0.f, 0.f, 0.f, 0.f, 0.f};
        #pragma unroll
        for (int w = 0; w < 16; ++w)
            #pragma unroll
            for (int i = 0; i < 6; ++i)
                acc[i] += sred[w * 6 + i];
        #pragma unroll
        for (int i = 0; i < 6; ++i)
            g_part[blk * 6 + i] = acc[i];
    }
}

// ---------------------------------------------------------------------------
// Kernel C: finalize BN stats once (1 block; warp w = channel w)
// ---------------------------------------------------------------------------
__global__ __launch_bounds__(288) void stats_kernel(
    const float* __restrict__ gamma, const float* __restrict__ beta)
{
    const int w = threadIdx.x >> 5, lane = threadIdx.x & 31;
    if (w >= 9) return;
    const int at = w / 3, d = w - at * 3;
    float sm = 0.f, sq = 0.f;
    for (int i = lane; i < NB * 2; i += 32) {
        const float* p = g_part + (size_t)(at * NB * 2 + i) * 6;
        sm += p[d];
        sq += p[3 + d];
    }
    #pragma unroll
    for (int off = 16; off > 0; off >>= 1) {
        sm += __shfl_down_sync(0xFFFFFFFFu, sm, off);
        sq += __shfl_down_sync(0xFFFFFFFFu, sq, off);
    }
    if (lane == 0) {
        const float mean = sm * (1.0f / NROWS);
        const float var  = sq * (1.0f / NROWS) - mean * mean;
        const float inv  = rsqrtf(var + 1e-5f);
        const float sc   = gamma[w] * inv;
        g_ss[w]     = sc;
        g_ss[9 + w] = beta[w] - mean * sc;
    }
}

// ---------------------------------------------------------------------------
// Kernel B: BN + FC. 4 consecutive rows/thread -> float4 LDG + float4 STG.
// ---------------------------------------------------------------------------
__global__ __launch_bounds__(256) void bnfc_kernel(
    const float* __restrict__ fcw, const float* __restrict__ fcb,
    float* __restrict__ out)
{
    __shared__ float ss[18];
    __shared__ float w[27];
    const int tid = threadIdx.x;
    if (tid < 18) ss[tid] = g_ss[tid];
    if (tid < 27) w[tid] = fcw[tid];
    __syncthreads();

    const int r0 = (blockIdx.x * 256 + tid) * 4;
    float n[4][9];
    #pragma unroll
    for (int c = 0; c < 9; ++c) {
        float4 v = *(const float4*)(g_att + (size_t)c * NROWS + r0);
        n[0][c] = fmaf(v.x, ss[c], ss[9 + c]);
        n[1][c] = fmaf(v.y, ss[c], ss[9 + c]);
        n[2][c] = fmaf(v.z, ss[c], ss[9 + c]);
        n[3][c] = fmaf(v.w, ss[c], ss[9 + c]);
    }
    float y[4][3];
    #pragma unroll
    for (int r = 0; r < 4; ++r)
        #pragma unroll
        for (int j = 0; j < 3; ++j) {
            float acc = fcb[j];
            #pragma unroll
            for (int c = 0; c < 9; ++c)
                acc = fmaf(n[r][c], w[j * 9 + c], acc);
            y[r][j] = acc;
        }
    float4* o = (float4*)(out + (size_t)r0 * 3);
    o[0] = make_float4(y[0][0], y[0][1], y[0][2], y[1][0]);
    o[1] = make_float4(y[1][1], y[1][2], y[2][0], y[2][1]);
    o[2] = make_float4(y[2][2], y[3][0], y[3][1], y[3][2]);
}

// ---------------------------------------------------------------------------
extern "C" void kernel_launch(void* const* d_in, const int* in_sizes, int n_in,
                              void* d_out, int out_size)
{
    const float* x     = (const float*)d_in[0];
    const float* WQ    = (const float*)d_in[1];
    const float* bQ    = (const float*)d_in[2];
    const float* WK    = (const float*)d_in[3];
    const float* bK    = (const float*)d_in[4];
    const float* WV    = (const float*)d_in[5];
    const float* bV    = (const float*)d_in[6];
    const float* gamma = (const float*)d_in[7];
    const float* beta  = (const float*)d_in[8];
    const float* fcw   = (const float*)d_in[9];
    const float* fcb   = (const float*)d_in[10];

    attn_kernel<<<NBLK_A, TPB_A>>>(x, WQ, bQ, WK, bK, WV, bV);
    stats_kernel<<<1, 288>>>(gamma, beta);
    bnfc_kernel<<<NROWS / 1024, 256>>>(fcw, fcb, (float*)d_out);
}